// round 1
// baseline (speedup 1.0000x reference)
#include <cuda_runtime.h>
#include <cstdint>

#define BATCH 32768
#define DIN   768
#define HID   3840
#define TOPK  64

// ---------------- scratch (__device__ globals: allocation-free) ----------------
__device__ float g_h[(size_t)BATCH * HID];        // dense encoder output (483 MB)
__device__ float g_wdecT[(size_t)HID * DIN];      // W_dec transposed [H, D]
__device__ int   g_tidx[(size_t)BATCH * TOPK];    // compact top-k indices
__device__ float g_tval[(size_t)BATCH * TOPK];    // compact top-k (relu'd) values

// ==================== encoder GEMM: h = (x - b_pre) @ W_enc^T + b_enc ====================
// M=32768, N=3840, K=768. Tile 128x128x16, 256 threads, 8x8 micro (4+4 split),
// double-buffered smem, one __syncthreads per K-tile.
__global__ void __launch_bounds__(256, 2) enc_gemm_kernel(
    const float* __restrict__ x, const float* __restrict__ W,
    const float* __restrict__ b_enc, const float* __restrict__ b_pre)
{
    __shared__ __align__(16) float As[2][16][128];
    __shared__ __align__(16) float Bs[2][16][128];

    const int bm = blockIdx.y * 128;
    const int bn = blockIdx.x * 128;
    const int tid = threadIdx.x;
    const int lr = tid >> 2;           // 0..63 (load row)
    const int lc = (tid & 3) << 2;     // 0,4,8,12 (load col, float4)
    const int tx = tid & 15;           // n sub-tile
    const int ty = tid >> 4;           // m sub-tile

    const float* Ap = x + (size_t)(bm + lr) * DIN + lc;
    const float* Bp = W + (size_t)(bn + lr) * DIN + lc;

    float4 ra0, ra1, rb0, rb1, rbp;

    // prefetch K-tile 0
    ra0 = *(const float4*)(Ap);
    ra1 = *(const float4*)(Ap + 64 * DIN);
    rbp = *(const float4*)(b_pre + lc);
    rb0 = *(const float4*)(Bp);
    rb1 = *(const float4*)(Bp + 64 * DIN);

    As[0][lc + 0][lr]      = ra0.x - rbp.x;
    As[0][lc + 1][lr]      = ra0.y - rbp.y;
    As[0][lc + 2][lr]      = ra0.z - rbp.z;
    As[0][lc + 3][lr]      = ra0.w - rbp.w;
    As[0][lc + 0][lr + 64] = ra1.x - rbp.x;
    As[0][lc + 1][lr + 64] = ra1.y - rbp.y;
    As[0][lc + 2][lr + 64] = ra1.z - rbp.z;
    As[0][lc + 3][lr + 64] = ra1.w - rbp.w;
    Bs[0][lc + 0][lr]      = rb0.x;
    Bs[0][lc + 1][lr]      = rb0.y;
    Bs[0][lc + 2][lr]      = rb0.z;
    Bs[0][lc + 3][lr]      = rb0.w;
    Bs[0][lc + 0][lr + 64] = rb1.x;
    Bs[0][lc + 1][lr + 64] = rb1.y;
    Bs[0][lc + 2][lr + 64] = rb1.z;
    Bs[0][lc + 3][lr + 64] = rb1.w;
    __syncthreads();

    float acc[8][8];
    #pragma unroll
    for (int i = 0; i < 8; ++i)
        #pragma unroll
        for (int j = 0; j < 8; ++j) acc[i][j] = 0.f;

    int buf = 0;
    const int NT = DIN / 16;  // 48 K-tiles

    #pragma unroll 1
    for (int t = 0; t < NT; ++t) {
        const bool has_next = (t + 1 < NT);
        if (has_next) {
            const int k0 = (t + 1) * 16;
            ra0 = *(const float4*)(Ap + k0);
            ra1 = *(const float4*)(Ap + 64 * DIN + k0);
            rbp = *(const float4*)(b_pre + k0 + lc);
            rb0 = *(const float4*)(Bp + k0);
            rb1 = *(const float4*)(Bp + 64 * DIN + k0);
        }

        #pragma unroll
        for (int k = 0; k < 16; ++k) {
            float fa[8], fb[8];
            *(float4*)&fa[0] = *(const float4*)&As[buf][k][ty * 4];
            *(float4*)&fa[4] = *(const float4*)&As[buf][k][64 + ty * 4];
            *(float4*)&fb[0] = *(const float4*)&Bs[buf][k][tx * 4];
            *(float4*)&fb[4] = *(const float4*)&Bs[buf][k][64 + tx * 4];
            #pragma unroll
            for (int i = 0; i < 8; ++i)
                #pragma unroll
                for (int j = 0; j < 8; ++j)
                    acc[i][j] = fmaf(fa[i], fb[j], acc[i][j]);
        }

        if (has_next) {
            const int nb = buf ^ 1;
            As[nb][lc + 0][lr]      = ra0.x - rbp.x;
            As[nb][lc + 1][lr]      = ra0.y - rbp.y;
            As[nb][lc + 2][lr]      = ra0.z - rbp.z;
            As[nb][lc + 3][lr]      = ra0.w - rbp.w;
            As[nb][lc + 0][lr + 64] = ra1.x - rbp.x;
            As[nb][lc + 1][lr + 64] = ra1.y - rbp.y;
            As[nb][lc + 2][lr + 64] = ra1.z - rbp.z;
            As[nb][lc + 3][lr + 64] = ra1.w - rbp.w;
            Bs[nb][lc + 0][lr]      = rb0.x;
            Bs[nb][lc + 1][lr]      = rb0.y;
            Bs[nb][lc + 2][lr]      = rb0.z;
            Bs[nb][lc + 3][lr]      = rb0.w;
            Bs[nb][lc + 0][lr + 64] = rb1.x;
            Bs[nb][lc + 1][lr + 64] = rb1.y;
            Bs[nb][lc + 2][lr + 64] = rb1.z;
            Bs[nb][lc + 3][lr + 64] = rb1.w;
        }
        __syncthreads();
        buf ^= 1;
    }

    // epilogue: add b_enc, store to g_h
    const float4 be0 = *(const float4*)(b_enc + bn + tx * 4);
    const float4 be1 = *(const float4*)(b_enc + bn + 64 + tx * 4);
    #pragma unroll
    for (int im = 0; im < 8; ++im) {
        const int m = bm + ((im < 4) ? (ty * 4 + im) : (64 + ty * 4 + im - 4));
        float* hrow = g_h + (size_t)m * HID + bn;
        float4 o0, o1;
        o0.x = acc[im][0] + be0.x; o0.y = acc[im][1] + be0.y;
        o0.z = acc[im][2] + be0.z; o0.w = acc[im][3] + be0.w;
        o1.x = acc[im][4] + be1.x; o1.y = acc[im][5] + be1.y;
        o1.z = acc[im][6] + be1.z; o1.w = acc[im][7] + be1.w;
        *(float4*)(hrow + tx * 4)      = o0;
        *(float4*)(hrow + 64 + tx * 4) = o1;
    }
}

// ==================== W_dec [D,H] -> W_decT [H,D] ====================
__global__ void transpose_kernel(const float* __restrict__ in)
{
    __shared__ float t[32][33];
    const int bx = blockIdx.x * 32;  // h
    const int by = blockIdx.y * 32;  // d
    const int x = bx + threadIdx.x;
    #pragma unroll
    for (int j = 0; j < 32; j += 8)
        t[threadIdx.y + j][threadIdx.x] = in[(size_t)(by + threadIdx.y + j) * HID + x];
    __syncthreads();
    const int x2 = by + threadIdx.x;
    #pragma unroll
    for (int j = 0; j < 32; j += 8)
        g_wdecT[(size_t)(bx + threadIdx.y + j) * DIN + x2] = t[threadIdx.x][threadIdx.y + j];
}

// ==================== per-row exact top-64 + scatter ====================
// Prefilter candidates (v > T0) into a compact list, then one warp does 64
// exact argmax passes over the candidates (ties -> lower index, matching
// jax.lax.top_k). If the candidate count is out of range (statistically
// ~never), fall back to exact selection over the full row.
#define T0FILT 1.55f
#define CAP    512

__global__ void __launch_bounds__(128) topk_kernel(float* __restrict__ h_sparse)
{
    const int row = blockIdx.x;
    __shared__ float sv[HID];
    __shared__ float cv[CAP];
    __shared__ int   ci[CAP];
    __shared__ int   s_cnt;
    __shared__ int   sel_i[TOPK];
    __shared__ float sel_v[TOPK];

    const int tid = threadIdx.x;
    const float* hr = g_h + (size_t)row * HID;
    if (tid == 0) s_cnt = 0;
    __syncthreads();

    for (int i = tid; i < HID / 4; i += 128) {
        float4 v = ((const float4*)hr)[i];
        ((float4*)sv)[i] = v;
        const int base = i * 4;
        if (v.x > T0FILT) { int p = atomicAdd(&s_cnt, 1); if (p < CAP) { cv[p] = v.x; ci[p] = base + 0; } }
        if (v.y > T0FILT) { int p = atomicAdd(&s_cnt, 1); if (p < CAP) { cv[p] = v.y; ci[p] = base + 1; } }
        if (v.z > T0FILT) { int p = atomicAdd(&s_cnt, 1); if (p < CAP) { cv[p] = v.z; ci[p] = base + 2; } }
        if (v.w > T0FILT) { int p = atomicAdd(&s_cnt, 1); if (p < CAP) { cv[p] = v.w; ci[p] = base + 3; } }
    }
    __syncthreads();
    const int cnt = s_cnt;
    const bool fallback = (cnt < TOPK) || (cnt > CAP);

    if (tid < 32) {
        if (!fallback) {
            for (int it = 0; it < TOPK; ++it) {
                float best = -3.0e38f; int bi = 0x7FFFFFFF; int bc = 0;
                for (int c = tid; c < cnt; c += 32) {
                    float v = cv[c]; int id = ci[c];
                    if (v > best || (v == best && id < bi)) { best = v; bi = id; bc = c; }
                }
                #pragma unroll
                for (int o = 16; o > 0; o >>= 1) {
                    float ov = __shfl_xor_sync(0xffffffffu, best, o);
                    int   oi = __shfl_xor_sync(0xffffffffu, bi, o);
                    int   oc = __shfl_xor_sync(0xffffffffu, bc, o);
                    if (ov > best || (ov == best && oi < bi)) { best = ov; bi = oi; bc = oc; }
                }
                if (tid == 0) {
                    cv[bc] = -3.0e38f;
                    sel_i[it] = bi;
                    sel_v[it] = best > 0.f ? best : 0.f;
                }
                __syncwarp();
            }
        } else {
            for (int it = 0; it < TOPK; ++it) {
                float best = -3.0e38f; int bi = 0x7FFFFFFF;
                for (int c = tid; c < HID; c += 32) {
                    float v = sv[c];
                    if (v > best || (v == best && c < bi)) { best = v; bi = c; }
                }
                #pragma unroll
                for (int o = 16; o > 0; o >>= 1) {
                    float ov = __shfl_xor_sync(0xffffffffu, best, o);
                    int   oi = __shfl_xor_sync(0xffffffffu, bi, o);
                    if (ov > best || (ov == best && oi < bi)) { best = ov; bi = oi; }
                }
                if (tid == 0) {
                    sv[bi] = -3.0e38f;
                    sel_i[it] = bi;
                    sel_v[it] = best > 0.f ? best : 0.f;
                }
                __syncwarp();
            }
        }
    }
    __syncthreads();

    // write dense h_sparse row: zeros then scatter
    float* orow = h_sparse + (size_t)row * HID;
    const float4 z4 = make_float4(0.f, 0.f, 0.f, 0.f);
    for (int i = tid; i < HID / 4; i += 128) ((float4*)orow)[i] = z4;
    __syncthreads();
    if (tid < TOPK) {
        orow[sel_i[tid]] = sel_v[tid];
        g_tidx[(size_t)row * TOPK + tid] = sel_i[tid];
        g_tval[(size_t)row * TOPK + tid] = sel_v[tid];
    }
}

// ==================== sparse decoder: x_rec = sum_k v_k * W_decT[idx_k,:] + b_pre ====================
__global__ void __launch_bounds__(192) dec_kernel(
    const float* __restrict__ b_pre, float* __restrict__ xrec)
{
    const int row = blockIdx.x;
    __shared__ int   si[TOPK];
    __shared__ float svl[TOPK];
    const int tid = threadIdx.x;
    if (tid < TOPK) {
        si[tid]  = g_tidx[(size_t)row * TOPK + tid];
        svl[tid] = g_tval[(size_t)row * TOPK + tid];
    }
    __syncthreads();

    float4 acc = ((const float4*)b_pre)[tid];  // 192 threads x float4 = 768
    #pragma unroll 4
    for (int k = 0; k < TOPK; ++k) {
        const float v = svl[k];
        const float4 wv = ((const float4*)(g_wdecT + (size_t)si[k] * DIN))[tid];
        acc.x = fmaf(v, wv.x, acc.x);
        acc.y = fmaf(v, wv.y, acc.y);
        acc.z = fmaf(v, wv.z, acc.z);
        acc.w = fmaf(v, wv.w, acc.w);
    }
    ((float4*)(xrec + (size_t)row * DIN))[tid] = acc;
}

// ==================== launch ====================
extern "C" void kernel_launch(void* const* d_in, const int* in_sizes, int n_in,
                              void* d_out, int out_size)
{
    const float* x     = (const float*)d_in[0];
    const float* W_enc = (const float*)d_in[1];
    const float* b_enc = (const float*)d_in[2];
    const float* W_dec = (const float*)d_in[3];
    const float* b_pre = (const float*)d_in[4];

    float* out      = (float*)d_out;
    float* xrec     = out;                              // [B, 768]
    float* h_sparse = out + (size_t)BATCH * DIN;        // [B, 3840]

    // independent prep: W_dec transpose
    transpose_kernel<<<dim3(HID / 32, DIN / 32), dim3(32, 8)>>>(W_dec);

    // encoder GEMM -> g_h
    dim3 gg(HID / 128, BATCH / 128);
    enc_gemm_kernel<<<gg, 256>>>(x, W_enc, b_enc, b_pre);

    // exact top-64 per row -> h_sparse + compact lists
    topk_kernel<<<BATCH, 128>>>(h_sparse);

    // sparse decoder -> xrec
    dec_kernel<<<BATCH, 192>>>(b_pre, xrec);
}

// round 8
// speedup vs baseline: 1.0747x; 1.0747x over previous
#include <cuda_runtime.h>
#include <cuda_bf16.h>
#include <cstdint>
#include <cstring>

#define BATCH 32768
#define DIN   768
#define HID   3840
#define TOPK  64

// ---------------- scratch ----------------
__device__ float g_h[(size_t)BATCH * HID];
__device__ float g_wdecT[(size_t)HID * DIN];
__device__ int   g_tidx[(size_t)BATCH * TOPK];
__device__ float g_tval[(size_t)BATCH * TOPK];

// ---------------- f32x2 packed-FMA helpers ----------------
#define FFMA2(d, a, b) \
    asm("fma.rn.f32x2 %0, %1, %2, %0;" : "+l"(d) : "l"(a), "l"(b))
#define PACK_DUP(d, x) \
    asm("mov.b64 %0, {%1, %1};" : "=l"(d) : "f"(x))
#define PACK2(d, x, y) \
    asm("mov.b64 %0, {%1, %2};" : "=l"(d) : "f"(x), "f"(y))

// ==================== encoder GEMM: h = (x - b_pre) @ W_enc^T + b_enc ====================
// 128x128x16 tile, 256 threads, 8x8 micro via f32x2 (32 FFMA2/k), double-buffered smem.
// Accumulation order per output element identical to the verified round-1 fp32 kernel.
__global__ void __launch_bounds__(256, 2) enc_gemm_kernel(
    const float* __restrict__ x, const float* __restrict__ W,
    const float* __restrict__ b_enc, const float* __restrict__ b_pre)
{
    __shared__ __align__(16) float As[2][16][128];
    __shared__ __align__(16) float Bs[2][16][128];

    const int bm = blockIdx.y * 128;
    const int bn = blockIdx.x * 128;
    const int tid = threadIdx.x;
    const int lr = tid >> 2;           // 0..63
    const int lc = (tid & 3) << 2;     // 0,4,8,12
    const int tx = tid & 15;
    const int ty = tid >> 4;

    const float* Ap = x + (size_t)(bm + lr) * DIN + lc;
    const float* Bp = W + (size_t)(bn + lr) * DIN + lc;

    float4 ra0, ra1, rb0, rb1, rbp;

    ra0 = *(const float4*)(Ap);
    ra1 = *(const float4*)(Ap + 64 * DIN);
    rbp = *(const float4*)(b_pre + lc);
    rb0 = *(const float4*)(Bp);
    rb1 = *(const float4*)(Bp + 64 * DIN);

    As[0][lc + 0][lr]      = ra0.x - rbp.x;
    As[0][lc + 1][lr]      = ra0.y - rbp.y;
    As[0][lc + 2][lr]      = ra0.z - rbp.z;
    As[0][lc + 3][lr]      = ra0.w - rbp.w;
    As[0][lc + 0][lr + 64] = ra1.x - rbp.x;
    As[0][lc + 1][lr + 64] = ra1.y - rbp.y;
    As[0][lc + 2][lr + 64] = ra1.z - rbp.z;
    As[0][lc + 3][lr + 64] = ra1.w - rbp.w;
    Bs[0][lc + 0][lr]      = rb0.x;
    Bs[0][lc + 1][lr]      = rb0.y;
    Bs[0][lc + 2][lr]      = rb0.z;
    Bs[0][lc + 3][lr]      = rb0.w;
    Bs[0][lc + 0][lr + 64] = rb1.x;
    Bs[0][lc + 1][lr + 64] = rb1.y;
    Bs[0][lc + 2][lr + 64] = rb1.z;
    Bs[0][lc + 3][lr + 64] = rb1.w;
    __syncthreads();

    // acc2[i][j] packs output cols {2j, 2j+1} of the 4-col groups (j<2: cols tx*4.., j>=2: cols 64+tx*4..)
    unsigned long long acc2[8][4];
    #pragma unroll
    for (int i = 0; i < 8; ++i)
        #pragma unroll
        for (int j = 0; j < 4; ++j) acc2[i][j] = 0ULL;

    int buf = 0;
    const int NT = DIN / 16;  // 48

    #pragma unroll 1
    for (int t = 0; t < NT; ++t) {
        const bool has_next = (t + 1 < NT);
        if (has_next) {
            const int k0 = (t + 1) * 16;
            ra0 = *(const float4*)(Ap + k0);
            ra1 = *(const float4*)(Ap + 64 * DIN + k0);
            rbp = *(const float4*)(b_pre + k0 + lc);
            rb0 = *(const float4*)(Bp + k0);
            rb1 = *(const float4*)(Bp + 64 * DIN + k0);
        }

        #pragma unroll
        for (int k = 0; k < 16; ++k) {
            float fa[8], fb[8];
            *(float4*)&fa[0] = *(const float4*)&As[buf][k][ty * 4];
            *(float4*)&fa[4] = *(const float4*)&As[buf][k][64 + ty * 4];
            *(float4*)&fb[0] = *(const float4*)&Bs[buf][k][tx * 4];
            *(float4*)&fb[4] = *(const float4*)&Bs[buf][k][64 + tx * 4];
            unsigned long long pb[4];
            #pragma unroll
            for (int j = 0; j < 4; ++j) PACK2(pb[j], fb[2 * j], fb[2 * j + 1]);
            #pragma unroll
            for (int i = 0; i < 8; ++i) {
                unsigned long long pa;
                PACK_DUP(pa, fa[i]);
                #pragma unroll
                for (int j = 0; j < 4; ++j)
                    FFMA2(acc2[i][j], pa, pb[j]);
            }
        }

        if (has_next) {
            const int nb = buf ^ 1;
            As[nb][lc + 0][lr]      = ra0.x - rbp.x;
            As[nb][lc + 1][lr]      = ra0.y - rbp.y;
            As[nb][lc + 2][lr]      = ra0.z - rbp.z;
            As[nb][lc + 3][lr]      = ra0.w - rbp.w;
            As[nb][lc + 0][lr + 64] = ra1.x - rbp.x;
            As[nb][lc + 1][lr + 64] = ra1.y - rbp.y;
            As[nb][lc + 2][lr + 64] = ra1.z - rbp.z;
            As[nb][lc + 3][lr + 64] = ra1.w - rbp.w;
            Bs[nb][lc + 0][lr]      = rb0.x;
            Bs[nb][lc + 1][lr]      = rb0.y;
            Bs[nb][lc + 2][lr]      = rb0.z;
            Bs[nb][lc + 3][lr]      = rb0.w;
            Bs[nb][lc + 0][lr + 64] = rb1.x;
            Bs[nb][lc + 1][lr + 64] = rb1.y;
            Bs[nb][lc + 2][lr + 64] = rb1.z;
            Bs[nb][lc + 3][lr + 64] = rb1.w;
        }
        __syncthreads();
        buf ^= 1;
    }

    // epilogue: add b_enc, store
    const float4 be0 = *(const float4*)(b_enc + bn + tx * 4);
    const float4 be1 = *(const float4*)(b_enc + bn + 64 + tx * 4);
    #pragma unroll
    for (int im = 0; im < 8; ++im) {
        const int m = bm + ((im < 4) ? (ty * 4 + im) : (64 + ty * 4 + im - 4));
        float* hrow = g_h + (size_t)m * HID + bn;
        float2 p0, p1, p2, p3;
        memcpy(&p0, &acc2[im][0], 8);
        memcpy(&p1, &acc2[im][1], 8);
        memcpy(&p2, &acc2[im][2], 8);
        memcpy(&p3, &acc2[im][3], 8);
        float4 o0, o1;
        o0.x = p0.x + be0.x; o0.y = p0.y + be0.y;
        o0.z = p1.x + be0.z; o0.w = p1.y + be0.w;
        o1.x = p2.x + be1.x; o1.y = p2.y + be1.y;
        o1.z = p3.x + be1.z; o1.w = p3.y + be1.w;
        *(float4*)(hrow + tx * 4)      = o0;
        *(float4*)(hrow + 64 + tx * 4) = o1;
    }
}

// ==================== W_dec [D,H] -> W_decT [H,D] ====================
__global__ void transpose_kernel(const float* __restrict__ in)
{
    __shared__ float t[32][33];
    const int bx = blockIdx.x * 32;  // h
    const int by = blockIdx.y * 32;  // d
    const int x = bx + threadIdx.x;
    #pragma unroll
    for (int j = 0; j < 32; j += 8)
        t[threadIdx.y + j][threadIdx.x] = in[(size_t)(by + threadIdx.y + j) * HID + x];
    __syncthreads();
    const int x2 = by + threadIdx.x;
    #pragma unroll
    for (int j = 0; j < 32; j += 8)
        g_wdecT[(size_t)(bx + threadIdx.y + j) * DIN + x2] = t[threadIdx.x][threadIdx.y + j];
}

// ==================== per-row exact top-64 + scatter (verified round-1 version) ====================
#define T0FILT 1.55f
#define CAP    512

__global__ void __launch_bounds__(128) topk_kernel(float* __restrict__ h_sparse)
{
    const int row = blockIdx.x;
    __shared__ float sv[HID];
    __shared__ float cv[CAP];
    __shared__ int   ci[CAP];
    __shared__ int   s_cnt;
    __shared__ int   sel_i[TOPK];
    __shared__ float sel_v[TOPK];

    const int tid = threadIdx.x;
    const float* hr = g_h + (size_t)row * HID;
    if (tid == 0) s_cnt = 0;
    __syncthreads();

    for (int i = tid; i < HID / 4; i += 128) {
        float4 v = ((const float4*)hr)[i];
        ((float4*)sv)[i] = v;
        const int base = i * 4;
        if (v.x > T0FILT) { int p = atomicAdd(&s_cnt, 1); if (p < CAP) { cv[p] = v.x; ci[p] = base + 0; } }
        if (v.y > T0FILT) { int p = atomicAdd(&s_cnt, 1); if (p < CAP) { cv[p] = v.y; ci[p] = base + 1; } }
        if (v.z > T0FILT) { int p = atomicAdd(&s_cnt, 1); if (p < CAP) { cv[p] = v.z; ci[p] = base + 2; } }
        if (v.w > T0FILT) { int p = atomicAdd(&s_cnt, 1); if (p < CAP) { cv[p] = v.w; ci[p] = base + 3; } }
    }
    __syncthreads();
    const int cnt = s_cnt;
    const bool fallback = (cnt < TOPK) || (cnt > CAP);

    if (tid < 32) {
        if (!fallback) {
            for (int it = 0; it < TOPK; ++it) {
                float best = -3.0e38f; int bi = 0x7FFFFFFF; int bc = 0;
                for (int c = tid; c < cnt; c += 32) {
                    float v = cv[c]; int id = ci[c];
                    if (v > best || (v == best && id < bi)) { best = v; bi = id; bc = c; }
                }
                #pragma unroll
                for (int o = 16; o > 0; o >>= 1) {
                    float ov = __shfl_xor_sync(0xffffffffu, best, o);
                    int   oi = __shfl_xor_sync(0xffffffffu, bi, o);
                    int   oc = __shfl_xor_sync(0xffffffffu, bc, o);
                    if (ov > best || (ov == best && oi < bi)) { best = ov; bi = oi; bc = oc; }
                }
                if (tid == 0) {
                    cv[bc] = -3.0e38f;
                    sel_i[it] = bi;
                    sel_v[it] = best > 0.f ? best : 0.f;
                }
                __syncwarp();
            }
        } else {
            for (int it = 0; it < TOPK; ++it) {
                float best = -3.0e38f; int bi = 0x7FFFFFFF;
                for (int c = tid; c < HID; c += 32) {
                    float v = sv[c];
                    if (v > best || (v == best && c < bi)) { best = v; bi = c; }
                }
                #pragma unroll
                for (int o = 16; o > 0; o >>= 1) {
                    float ov = __shfl_xor_sync(0xffffffffu, best, o);
                    int   oi = __shfl_xor_sync(0xffffffffu, bi, o);
                    if (ov > best || (ov == best && oi < bi)) { best = ov; bi = oi; }
                }
                if (tid == 0) {
                    sv[bi] = -3.0e38f;
                    sel_i[it] = bi;
                    sel_v[it] = best > 0.f ? best : 0.f;
                }
                __syncwarp();
            }
        }
    }
    __syncthreads();

    float* orow = h_sparse + (size_t)row * HID;
    const float4 z4 = make_float4(0.f, 0.f, 0.f, 0.f);
    for (int i = tid; i < HID / 4; i += 128) ((float4*)orow)[i] = z4;
    __syncthreads();
    if (tid < TOPK) {
        orow[sel_i[tid]] = sel_v[tid];
        g_tidx[(size_t)row * TOPK + tid] = sel_i[tid];
        g_tval[(size_t)row * TOPK + tid] = sel_v[tid];
    }
}

// ==================== sparse decoder ====================
__global__ void __launch_bounds__(192) dec_kernel(
    const float* __restrict__ b_pre, float* __restrict__ xrec)
{
    const int row = blockIdx.x;
    __shared__ int   si[TOPK];
    __shared__ float svl[TOPK];
    const int tid = threadIdx.x;
    if (tid < TOPK) {
        si[tid]  = g_tidx[(size_t)row * TOPK + tid];
        svl[tid] = g_tval[(size_t)row * TOPK + tid];
    }
    __syncthreads();

    float4 acc = ((const float4*)b_pre)[tid];
    #pragma unroll 4
    for (int k = 0; k < TOPK; ++k) {
        const float v = svl[k];
        const float4 wv = ((const float4*)(g_wdecT + (size_t)si[k] * DIN))[tid];
        acc.x = fmaf(v, wv.x, acc.x);
        acc.y = fmaf(v, wv.y, acc.y);
        acc.z = fmaf(v, wv.z, acc.z);
        acc.w = fmaf(v, wv.w, acc.w);
    }
    ((float4*)(xrec + (size_t)row * DIN))[tid] = acc;
}

// ==================== launch ====================
extern "C" void kernel_launch(void* const* d_in, const int* in_sizes, int n_in,
                              void* d_out, int out_size)
{
    const float* x     = (const float*)d_in[0];
    const float* W_enc = (const float*)d_in[1];
    const float* b_enc = (const float*)d_in[2];
    const float* W_dec = (const float*)d_in[3];
    const float* b_pre = (const float*)d_in[4];

    float* out      = (float*)d_out;
    float* xrec     = out;                        // [B, 768]
    float* h_sparse = out + (size_t)BATCH * DIN;  // [B, 3840]

    transpose_kernel<<<dim3(HID / 32, DIN / 32), dim3(32, 8)>>>(W_dec);

    dim3 gg(HID / 128, BATCH / 128);
    enc_gemm_kernel<<<gg, 256>>>(x, W_enc, b_enc, b_pre);

    topk_kernel<<<BATCH, 128>>>(h_sparse);
    dec_kernel<<<BATCH, 192>>>(b_pre, xrec);
}